// round 14
// baseline (speedup 1.0000x reference)
#include <cuda_runtime.h>
#include <math.h>

#define H        64
#define NZ       120
#define NLAYERS  4
#define DIMH     256
#define DIMG     65536

#define TB_BLKS  120            // table blocks (phase A)
#define HB_BLKS  256            // histogram blocks (phase A)
#define GRID     (TB_BLKS + HB_BLKS)    // 376
#define ROWW     65             // padded row width (words) per bin

// Scratch (no allocations allowed)
__device__ int      d_hist[NZ];         // global histogram (int atomics =
                                        // deterministic; phase C re-zeroes)
__device__ float    d_ftab[NZ * H];     // UNWEIGHTED post-layer table f_z
__device__ float    d_gbuf[DIMG];       // unsymmetrized g
__device__ unsigned d_cnt = 0;          // monotonic ticket counter; each
                                        // barrier consumes exactly GRID
                                        // tickets -> replay-deterministic

// Device-wide ticket barrier (validated in R13: cost ~ one launch boundary).
__device__ __forceinline__ void gbar() {
    __threadfence();                    // publish this block's global writes
    __syncthreads();                    // whole block arrived
    if (threadIdx.x == 0) {
        unsigned my = atomicAdd(&d_cnt, 1u);
        unsigned target = (my / GRID + 1u) * GRID;
        while (atomicAdd(&d_cnt, 0u) < target) { }
    }
    __syncthreads();
    __threadfence();                    // acquire peers' global writes
}

// ---------------------------------------------------------------------------
// ONE kernel, two ticket barriers. Phase A = R12's kA (verified 13.2->7.0us).
// Phase B = kB phase 1 (gf reduce + matvecs). Phase C = 8-fold symmetrization.
// Removes the last inter-kernel boundary; occupancy unconstrained (33KB smem,
// ~40 regs, 2.5 blocks/SM needed vs ~7 possible).
// ---------------------------------------------------------------------------
__global__ void __launch_bounds__(256)
kfused(const int* __restrict__ Z, int n,
       const float* __restrict__ embed, const float* __restrict__ W_tp,
       const float* __restrict__ w_g,   const float* __restrict__ b_g,
       const float* __restrict__ w_h,   const float* __restrict__ b_h,
       float* __restrict__ out) {
    __shared__ unsigned int cnt32[NZ * ROWW];   // 31,200 B (phase A hist)
    __shared__ float scnt[NZ];
    __shared__ float gf[H];
    __shared__ float red[256];
    const int t   = threadIdx.x;
    const int bid = blockIdx.x;

    // ======================= Phase A: table + histogram ====================
    if (bid < TB_BLKS) {
        // ---- layer table: 256 threads, k split 4 ways ----
        __shared__ float xs[H];
        const int j = t & 63, p = t >> 6;
        if (t < H) xs[t] = embed[bid * H + t];
        __syncthreads();

        #pragma unroll
        for (int l = 0; l < NLAYERS; ++l) {
            const float* __restrict__ W = W_tp + l * H * H + p * 16 * H;
            float a = 0.f;
            #pragma unroll
            for (int kk = 0; kk < 16; ++kk)         // 16 independent W loads
                a = fmaf(xs[p * 16 + kk], W[kk * H + j], a);
            red[t] = a;
            __syncthreads();
            if (t < H) {
                float s = (red[t] + red[t + 64] + red[t + 128] + red[t + 192])
                          * 0.125f;                 // INV_SQRT_H = 1/sqrt(64)
                xs[t] = s / (1.f + expf(-s));       // silu
            }
            __syncthreads();
        }
        if (t < H) d_ftab[bid * H + t] = xs[t];
    } else {
        // ---- histogram: private byte counters, batched loads ----
        unsigned char* cnt8 = (unsigned char*)cnt32;
        const int hb = bid - TB_BLKS;

        for (int i = t; i < NZ * ROWW; i += 256) cnt32[i] = 0;

        // dtype sniff, warp-parallel (Z may be int32 or int64 per JAX x64;
        // int64 LE data (<120) has every odd word == 0)
        const int lane = t & 31;
        const int probe = Z[2 * lane + 1];
        const unsigned nzmask = __ballot_sync(0xffffffffu, probe != 0);
        const bool is64 = (nzmask == 0u);
        __syncthreads();

        const int4* __restrict__ Z4 = (const int4*)Z;
        const int tid = hb * 256 + t;

#define BUMP4(v) { cnt8[(v).x * 260 + t]++; cnt8[(v).y * 260 + t]++; \
                   cnt8[(v).z * 260 + t]++; cnt8[(v).w * 260 + t]++; }
#define BUMP2(v) { cnt8[(v).x * 260 + t]++; cnt8[(v).z * 260 + t]++; }

        if (!is64) {
            const int n4 = n >> 2;
            const int base = tid * 4;               // 4 consecutive int4
            if (base + 3 < n4) {
                int4 v0 = Z4[base], v1 = Z4[base + 1],
                     v2 = Z4[base + 2], v3 = Z4[base + 3];   // MLP = 4
                BUMP4(v0) BUMP4(v1) BUMP4(v2) BUMP4(v3)
            } else {
                for (int i = base; i < n4; ++i) { int4 v = Z4[i]; BUMP4(v) }
            }
        } else {
            const int n2 = n >> 1;
            const int base = tid * 8;               // 8 consecutive int4
            if (base + 7 < n2) {
                int4 v0 = Z4[base],     v1 = Z4[base + 1],
                     v2 = Z4[base + 2], v3 = Z4[base + 3],
                     v4 = Z4[base + 4], v5 = Z4[base + 5],
                     v6 = Z4[base + 6], v7 = Z4[base + 7];   // MLP = 8
                BUMP2(v0) BUMP2(v1) BUMP2(v2) BUMP2(v3)
                BUMP2(v4) BUMP2(v5) BUMP2(v6) BUMP2(v7)
            } else {
                for (int i = base; i < n2; ++i) { int4 v = Z4[i]; BUMP2(v) }
            }
        }
#undef BUMP4
#undef BUMP2
        __syncthreads();

        // per-bin byte-sum via dp4a, ONE deterministic global add per bin
        if (t < NZ) {
            unsigned int acc = 0;
            #pragma unroll
            for (int w = 0; w < ROWW; ++w)
                acc = __dp4a(cnt32[t * ROWW + w], 0x01010101u, acc);
            atomicAdd(&d_hist[t], (int)acc);
        }
    }

    gbar();     // ===== barrier 1: d_ftab + d_hist complete =====

    // ======================= Phase B: gf + matvecs =========================
    if (bid < 257) {
        if (t < NZ) scnt[t] = (float)d_hist[t];
        __syncthreads();

        {   // gf[j] = sum_z scnt[z] * f_z[j]; 4 strips of 30 z's
            const int j = t & 63, p = t >> 6;
            float s = 0.f;
            #pragma unroll
            for (int z = p * 30; z < p * 30 + 30; ++z)
                s = fmaf(scnt[z], d_ftab[z * H + j], s);
            red[t] = s;
            __syncthreads();
            if (t < H)
                gf[t] = red[t] + red[t + 64] + red[t + 128] + red[t + 192];
            __syncthreads();
        }

        if (bid < 256) {
            const int i = bid * 256 + t;
            float acc = b_g[i];
            #pragma unroll
            for (int k = 0; k < H; ++k)
                acc = fmaf(gf[k], w_g[k * DIMG + i], acc);
            d_gbuf[i] = acc;
        } else {
            float acc = b_h[t];
            #pragma unroll
            for (int k = 0; k < H; ++k)
                acc = fmaf(gf[k], w_h[k * DIMH + t], acc);
            red[t] = acc;
            __syncthreads();
            const int i = t >> 4, j = t & 15;
            out[t] = 0.5f * (red[i * 16 + j] + red[j * 16 + i]);
        }
    }

    gbar();     // ===== barrier 2: d_gbuf complete =====

    // ======================= Phase C: 8-fold symmetrization ================
    if (bid < 256) {
        const int idx = bid * 256 + t;
        const int a = idx >> 12, b = (idx >> 8) & 15,
                  c = (idx >> 4) & 15, d = idx & 15;
#define GIDX(x, y, zz, w) d_gbuf[((x) << 12) | ((y) << 8) | ((zz) << 4) | (w)]
        float s = GIDX(a, b, c, d) + GIDX(b, a, c, d)
                + GIDX(a, b, d, c) + GIDX(b, a, d, c)
                + GIDX(c, d, a, b) + GIDX(d, c, a, b)
                + GIDX(c, d, b, a) + GIDX(d, c, b, a);
#undef GIDX
        out[256 + idx] = 0.125f * s;
    } else if (bid == 256) {
        if (t < NZ) d_hist[t] = 0;          // reset for next graph replay
    }
}

// ---------------------------------------------------------------------------
// Inputs (metadata order): Z, pos, ghost, embed, W_tp, w_h, b_h, w_g, b_g.
// pos and ghost are dead code in the reference -- never touched.
// ---------------------------------------------------------------------------
extern "C" void kernel_launch(void* const* d_in, const int* in_sizes, int n_in,
                              void* d_out, int out_size) {
    const int*   Z     = (const int*)d_in[0];
    const float* embed = (const float*)d_in[3];
    const float* W_tp  = (const float*)d_in[4];
    const float* w_h   = (const float*)d_in[5];
    const float* b_h   = (const float*)d_in[6];
    const float* w_g   = (const float*)d_in[7];
    const float* b_g   = (const float*)d_in[8];
    float* out = (float*)d_out;
    const int n = in_sizes[0];

    kfused<<<GRID, 256>>>(Z, n, embed, W_tp, w_g, b_g, w_h, b_h, out);
}

// round 16
// speedup vs baseline: 1.0199x; 1.0199x over previous
#include <cuda_runtime.h>
#include <math.h>

#define H        64
#define NZ       120
#define NLAYERS  4
#define DIMH     256
#define DIMG     65536

#define TB_BLKS  120            // table blocks in kA
#define HB_BLKS  512            // histogram blocks in kA (8 values/thread)
#define GRIDA    (TB_BLKS + HB_BLKS)
#define ROWW     65             // padded row width (words) per bin

// Scratch (no allocations allowed)
__device__ int   d_hist[NZ];            // global histogram (int atomics =
                                        // deterministic; k4 re-zeroes it)
__device__ float d_ftab[NZ * H];        // UNWEIGHTED post-layer table f_z
__device__ float d_gbuf[DIMG];          // unsymmetrized g

// ---------------------------------------------------------------------------
// kA: two INDEPENDENT jobs in one launch (632 blocks).
//  - table: W loads for layer l+1 prefetched during layer l (1 latency
//    exposure instead of 4)
//  - hist: 512 blocks -> 8-deep byte-RMW chain; sniff probe overlapped with
//    the smem zero loop; Z batch loads issued before the (now UNIFORM)
//    __syncthreads -- R15 deadlocked because the sync sat inside a divergent
//    branch in the block straddling the n4 boundary.
// ---------------------------------------------------------------------------
__global__ void __launch_bounds__(256)
kA(const int* __restrict__ Z, int n,
   const float* __restrict__ embed, const float* __restrict__ W_tp) {
    const int t   = threadIdx.x;
    const int bid = blockIdx.x;

    if (bid < TB_BLKS) {
        // ---- layer table: 256 threads, k split 4 ways, depth-1 pipeline ----
        __shared__ float xs[H];
        __shared__ float red[256];
        const int j = t & 63, p = t >> 6;
        if (t < H) xs[t] = embed[bid * H + t];

        float w[16];
        {   // prefetch layer 0 W slice (overlaps the embed load + sync)
            const float* __restrict__ W0 = W_tp + p * 16 * H;
            #pragma unroll
            for (int kk = 0; kk < 16; ++kk) w[kk] = W0[kk * H + j];
        }
        __syncthreads();

        #pragma unroll
        for (int l = 0; l < NLAYERS; ++l) {
            float wn[16];
            if (l < NLAYERS - 1) {      // prefetch next layer during compute
                const float* __restrict__ Wn = W_tp + (l + 1) * H * H + p * 16 * H;
                #pragma unroll
                for (int kk = 0; kk < 16; ++kk) wn[kk] = Wn[kk * H + j];
            }
            float a = 0.f;
            #pragma unroll
            for (int kk = 0; kk < 16; ++kk)
                a = fmaf(xs[p * 16 + kk], w[kk], a);
            red[t] = a;
            __syncthreads();
            if (t < H) {
                float s = (red[t] + red[t + 64] + red[t + 128] + red[t + 192])
                          * 0.125f;                 // INV_SQRT_H = 1/sqrt(64)
                xs[t] = s / (1.f + expf(-s));       // silu
            }
            __syncthreads();
            if (l < NLAYERS - 1) {
                #pragma unroll
                for (int kk = 0; kk < 16; ++kk) w[kk] = wn[kk];
            }
        }
        if (t < H) d_ftab[bid * H + t] = xs[t];
    } else {
        // ---- histogram: private byte counters, all latencies overlapped ----
        __shared__ unsigned int cnt32[NZ * ROWW];   // 31,200 B
        unsigned char* cnt8 = (unsigned char*)cnt32;
        const int hb = bid - TB_BLKS;
        const int lane = t & 31;

        // 1) issue sniff probe load FIRST (Z may be int32 or int64 per JAX
        //    x64; int64 LE data (<120) has every odd word == 0)
        const int probe = Z[2 * lane + 1];

        // 2) zero counters while the probe is in flight
        for (int i = t; i < NZ * ROWW; i += 256) cnt32[i] = 0;

        // 3) consume probe
        const unsigned nzmask = __ballot_sync(0xffffffffu, probe != 0);
        const bool is64 = (nzmask == 0u);

        const int4* __restrict__ Z4 = (const int4*)Z;
        const int tid = hb * 256 + t;

#define BUMP4(v) { cnt8[(v).x * 260 + t]++; cnt8[(v).y * 260 + t]++; \
                   cnt8[(v).z * 260 + t]++; cnt8[(v).w * 260 + t]++; }
#define BUMP2(v) { cnt8[(v).x * 260 + t]++; cnt8[(v).z * 260 + t]++; }

        // 4) predicated batch loads into registers (in flight during sync),
        //    then ONE uniform __syncthreads, then predicated increments.
        int4 v0 = make_int4(0, 0, 0, 0), v1 = v0, v2 = v0, v3 = v0;
        int nv = 0;                      // how many int4 this thread holds
        if (!is64) {
            const int n4 = n >> 2;                  // 250,000 int4
            const int base = tid * 2;               // 2 int4 = 8 values/thread
            if (base + 1 < n4)      { v0 = Z4[base]; v1 = Z4[base + 1]; nv = 2; }
            else if (base < n4)     { v0 = Z4[base]; nv = 1; }
            __syncthreads();            // UNIFORM: zeros visible to all
            if (nv > 0) BUMP4(v0)
            if (nv > 1) BUMP4(v1)
        } else {
            const int n2 = n >> 1;                  // int4 covers 2 int64
            const int base = tid * 4;               // 4 int4 = 8 values/thread
            if (base + 3 < n2) {
                v0 = Z4[base];     v1 = Z4[base + 1];
                v2 = Z4[base + 2]; v3 = Z4[base + 3]; nv = 4;
            } else {
                if (base     < n2) { v0 = Z4[base];     nv = 1; }
                if (base + 1 < n2) { v1 = Z4[base + 1]; nv = 2; }
                if (base + 2 < n2) { v2 = Z4[base + 2]; nv = 3; }
            }
            __syncthreads();            // UNIFORM
            if (nv > 0) BUMP2(v0)
            if (nv > 1) BUMP2(v1)
            if (nv > 2) BUMP2(v2)
            if (nv > 3) BUMP2(v3)
        }
#undef BUMP4
#undef BUMP2
        __syncthreads();

        // per-bin byte-sum via dp4a on the padded (conflict-free) row,
        // then ONE deterministic global integer add per bin per block.
        if (t < NZ) {
            unsigned int acc = 0;
            #pragma unroll
            for (int w2 = 0; w2 < ROWW; ++w2)
                acc = __dp4a(cnt32[t * ROWW + w2], 0x01010101u, acc);
            atomicAdd(&d_hist[t], (int)acc);
        }
    }
}

// ---------------------------------------------------------------------------
// k3 (grid 257): every block redundantly builds gf from d_hist/d_ftab
// (tiny, L2-hot). Blocks 0..255: g = gf @ w_g + b_g (w_g L2-resident across
// graph replays in the timed run). Block 256: h matvec + h symmetrization.
// (Byte-identical to R12's k3 -- best measured config.)
// ---------------------------------------------------------------------------
__global__ void __launch_bounds__(256)
k3(const float* __restrict__ w_g, const float* __restrict__ b_g,
   const float* __restrict__ w_h, const float* __restrict__ b_h,
   float* __restrict__ out) {
    __shared__ float scnt[NZ];
    __shared__ float gf[H];
    __shared__ float red[DIMH];
    const int t = threadIdx.x;

    if (t < NZ) scnt[t] = (float)d_hist[t];
    __syncthreads();

    {   // gf[j] = sum_z scnt[z] * f_z[j]; 4 strips of 30 z's per feature j
        const int j = t & 63, p = t >> 6;
        float s = 0.f;
        #pragma unroll
        for (int z = p * 30; z < p * 30 + 30; ++z)
            s = fmaf(scnt[z], d_ftab[z * H + j], s);
        red[t] = s;
        __syncthreads();
        if (t < H) gf[t] = red[t] + red[t + 64] + red[t + 128] + red[t + 192];
        __syncthreads();
    }

    if (blockIdx.x < 256) {
        const int i = blockIdx.x * 256 + t;
        float acc = b_g[i];
        #pragma unroll
        for (int k = 0; k < H; ++k)
            acc = fmaf(gf[k], w_g[k * DIMG + i], acc);
        d_gbuf[i] = acc;
    } else {
        float acc = b_h[t];
        #pragma unroll
        for (int k = 0; k < H; ++k)
            acc = fmaf(gf[k], w_h[k * DIMH + t], acc);
        red[t] = acc;
        __syncthreads();
        const int i = t >> 4, j = t & 15;
        out[t] = 0.5f * (red[i * 16 + j] + red[j * 16 + i]);
    }
}

// ---------------------------------------------------------------------------
// k4: 8-fold permutation symmetrization of g (d_gbuf is L2-hot, 256 KB).
// Block 0 also re-zeroes d_hist for the next graph replay (stream-ordered).
// ---------------------------------------------------------------------------
__global__ void __launch_bounds__(256)
k4(float* __restrict__ out) {
    if (blockIdx.x == 0 && threadIdx.x < NZ) d_hist[threadIdx.x] = 0;

    const int idx = blockIdx.x * 256 + threadIdx.x;
    const int a = idx >> 12, b = (idx >> 8) & 15, c = (idx >> 4) & 15, d = idx & 15;
#define GIDX(x, y, zz, w) d_gbuf[((x) << 12) | ((y) << 8) | ((zz) << 4) | (w)]
    float s = GIDX(a, b, c, d) + GIDX(b, a, c, d)
            + GIDX(a, b, d, c) + GIDX(b, a, d, c)
            + GIDX(c, d, a, b) + GIDX(d, c, a, b)
            + GIDX(c, d, b, a) + GIDX(d, c, b, a);
#undef GIDX
    out[256 + idx] = 0.125f * s;
}

// ---------------------------------------------------------------------------
// Inputs (metadata order): Z, pos, ghost, embed, W_tp, w_h, b_h, w_g, b_g.
// pos and ghost are dead code in the reference -- never touched.
// ---------------------------------------------------------------------------
extern "C" void kernel_launch(void* const* d_in, const int* in_sizes, int n_in,
                              void* d_out, int out_size) {
    const int*   Z     = (const int*)d_in[0];
    const float* embed = (const float*)d_in[3];
    const float* W_tp  = (const float*)d_in[4];
    const float* w_h   = (const float*)d_in[5];
    const float* b_h   = (const float*)d_in[6];
    const float* w_g   = (const float*)d_in[7];
    const float* b_g   = (const float*)d_in[8];
    float* out = (float*)d_out;
    const int n = in_sizes[0];

    kA<<<GRIDA, 256>>>(Z, n, embed, W_tp);
    k3<<<257, 256>>>(w_g, b_g, w_h, b_h, out);
    k4<<<256, 256>>>(out);
}